// round 15
// baseline (speedup 1.0000x reference)
#include <cuda_runtime.h>

// out[0:100]   = dot(I[row,:], p), row = inds1[m,0]*28 + inds1[m,1]
// out[100:200] = dot(J[row,:], p), P = 50000.
//
// v13: R7 skeleton (400x512, SPLIT=8, RPB=4, occ3, single wave) with
// PER-GROUP completion tickets: the last of the 8 blocks in each group
// reduces only its own 4 outputs (one warp, 32 lanes = 4 rows x 8 partials).
// 49 of the 50 reduction tails overlap with other groups' compute.

#define P_DIM     50000
#define P_VEC4    (P_DIM / 4)       // 12500 float4 per row
#define SPLIT     8
#define CARD2     100
#define NOUT      (2 * CARD2)       // 200
#define RPB       4                 // rows per block
#define NGROUPS   (NOUT / RPB)      // 50
#define NBLOCKS   (NGROUPS * SPLIT) // 400
#define W_IMG     28
#define NTHREADS  512
#define NWARPS    (NTHREADS / 32)

__device__ float        g_partials[NGROUPS][RPB][SPLIT];
__device__ unsigned int g_ticket[NGROUPS];   // zero-initialized; reset after use

// 12500 = 8*1562 + 4 -> first 4 chunks have 1563 float4, rest 1562
__device__ __forceinline__ int chunk_start(int c) { return c * 1562 + (c < 4 ? c : 4); }

__global__ __launch_bounds__(NTHREADS, 3)
void gather_dot_v13(const float* __restrict__ p,
                    const float* __restrict__ I,
                    const float* __restrict__ J,
                    const int*   __restrict__ inds1,
                    const int*   __restrict__ inds2,
                    float*       __restrict__ out)
{
    const int group = blockIdx.x / SPLIT;   // 0..49
    const int chunk = blockIdx.x % SPLIT;   // 0..7
    const int mbase = group * RPB;          // never straddles the I/J boundary

    const float* mat;
    const int*   ind;
    if (mbase < CARD2) { mat = I; ind = inds1 + 2 * mbase; }
    else               { mat = J; ind = inds2 + 2 * (mbase - CARD2); }

    const float4* __restrict__ pp = reinterpret_cast<const float4*>(p);
    const float4* __restrict__ r0;
    const float4* __restrict__ r1;
    const float4* __restrict__ r2;
    const float4* __restrict__ r3;
    {
        int row0 = __ldg(&ind[0]) * W_IMG + __ldg(&ind[1]);
        int row1 = __ldg(&ind[2]) * W_IMG + __ldg(&ind[3]);
        int row2 = __ldg(&ind[4]) * W_IMG + __ldg(&ind[5]);
        int row3 = __ldg(&ind[6]) * W_IMG + __ldg(&ind[7]);
        r0 = reinterpret_cast<const float4*>(mat + (size_t)row0 * P_DIM);
        r1 = reinterpret_cast<const float4*>(mat + (size_t)row1 * P_DIM);
        r2 = reinterpret_cast<const float4*>(mat + (size_t)row2 * P_DIM);
        r3 = reinterpret_cast<const float4*>(mat + (size_t)row3 * P_DIM);
    }

    const int c0 = chunk_start(chunk);
    const int c1 = chunk_start(chunk + 1);

    float s0 = 0.0f, s1 = 0.0f, s2 = 0.0f, s3 = 0.0f;

    // ~1562 float4 / 512 threads -> ~3 iterations, 5 independent 16B loads/iter.
    for (int i = c0 + (int)threadIdx.x; i < c1; i += NTHREADS) {
        float4 pv = pp[i];
        float4 a0 = r0[i];
        float4 a1 = r1[i];
        float4 a2 = r2[i];
        float4 a3 = r3[i];
        s0 += a0.x * pv.x + a0.y * pv.y + a0.z * pv.z + a0.w * pv.w;
        s1 += a1.x * pv.x + a1.y * pv.y + a1.z * pv.z + a1.w * pv.w;
        s2 += a2.x * pv.x + a2.y * pv.y + a2.z * pv.z + a2.w * pv.w;
        s3 += a3.x * pv.x + a3.y * pv.y + a3.z * pv.z + a3.w * pv.w;
    }

    // Warp reduction of the 4 accumulators
    #pragma unroll
    for (int off = 16; off > 0; off >>= 1) {
        s0 += __shfl_xor_sync(0xFFFFFFFFu, s0, off);
        s1 += __shfl_xor_sync(0xFFFFFFFFu, s1, off);
        s2 += __shfl_xor_sync(0xFFFFFFFFu, s2, off);
        s3 += __shfl_xor_sync(0xFFFFFFFFu, s3, off);
    }

    __shared__ float ws[RPB][NWARPS];
    __shared__ bool  s_last;
    const int lane = threadIdx.x & 31;
    const int wid  = threadIdx.x >> 5;
    if (lane == 0) { ws[0][wid] = s0; ws[1][wid] = s1; ws[2][wid] = s2; ws[3][wid] = s3; }
    __syncthreads();

    // Warps 0..3 each finish one accumulator (16 values -> 1) and publish it.
    if (wid < RPB && lane < NWARPS) {
        float v = ws[wid][lane];
        #pragma unroll
        for (int off = NWARPS / 2; off > 0; off >>= 1)
            v += __shfl_xor_sync(0xFFFFu, v, off);
        if (lane == 0)
            g_partials[group][wid][chunk] = v;
    }
    __syncthreads();          // this block's 4 partial writes issued

    // Per-group ticket: last of the 8 blocks in this group reduces its 4 outs.
    __threadfence();          // partials visible before the arrival is
    if (threadIdx.x == 0) {
        unsigned int t = atomicAdd(&g_ticket[group], 1u);
        s_last = (t == SPLIT - 1);
    }
    __syncthreads();

    if (s_last && wid == 0) {
        // 32 lanes = 4 rows x 8 chunks; xor-shuffle sums each 8-lane octet.
        const int r = lane >> 3;           // 0..3
        const int c = lane & 7;            // 0..7
        float v = __ldcg(&g_partials[group][r][c]);
        #pragma unroll
        for (int off = 4; off > 0; off >>= 1)
            v += __shfl_xor_sync(0xFFFFFFFFu, v, off);
        if (c == 0) out[mbase + r] = v;
        if (lane == 0) g_ticket[group] = 0;   // reset for next (deterministic) call
    }
}

extern "C" void kernel_launch(void* const* d_in, const int* in_sizes, int n_in,
                              void* d_out, int out_size)
{
    const float* p     = (const float*)d_in[0];   // [50000]
    const float* I     = (const float*)d_in[1];   // [784, 50000]
    const float* J     = (const float*)d_in[2];   // [784, 50000]
    const int*   inds1 = (const int*)  d_in[3];   // [100, 2]
    const int*   inds2 = (const int*)  d_in[4];   // [100, 2]
    float*       out   = (float*)d_out;           // [200]

    gather_dot_v13<<<NBLOCKS, NTHREADS>>>(p, I, J, inds1, inds2, out);
}